// round 1
// baseline (speedup 1.0000x reference)
#include <cuda_runtime.h>

#define NN 50000
#define NE 500000
#define HH 128
// per-node row stride in floats: 4*H = 512

// Scratch (device globals — allocation-free rule)
__device__ float g_agg[NN * 512];            // aggregated raw neighbor features
__device__ float g_Wt[4 * HH * HH];          // transposed weights [m][k][o]
                                             // m: 0=W_s_root 1=W_s_rel 2=W_v_root 3=W_v_rel
__device__ int g_is64;                       // edge_index dtype flag

// ---------------------------------------------------------------------------
__global__ void zero_agg_kernel() {
    float4* p = reinterpret_cast<float4*>(g_agg);
    int n4 = NN * 128;
    int i = blockIdx.x * blockDim.x + threadIdx.x;
    if (i < n4) p[i] = make_float4(0.f, 0.f, 0.f, 0.f);
}

// ---------------------------------------------------------------------------
// Detect whether edge_index is int64 (JAX x64 on) or int32 (default).
// If int64, the int32 view has zero high words at odd slots (values < 2^31).
__global__ void probe_dtype_kernel(const int* __restrict__ ei32) {
    if (threadIdx.x == 0 && blockIdx.x == 0) {
        int all_zero = 1;
        #pragma unroll
        for (int i = 0; i < 32; i++)
            if (ei32[2 * i + 1] != 0) all_zero = 0;
        g_is64 = all_zero;
    }
}

// ---------------------------------------------------------------------------
__global__ void transpose_w_kernel(const float* __restrict__ Wsroot,
                                   const float* __restrict__ Wsrel,
                                   const float* __restrict__ Wvroot,
                                   const float* __restrict__ Wvrel) {
    int t = blockIdx.x * blockDim.x + threadIdx.x;
    if (t >= 4 * HH * HH) return;
    int m = t >> 14;
    int rest = t & (HH * HH - 1);
    int o = rest >> 7;
    int k = rest & 127;
    const float* src = (m == 0) ? Wsroot : (m == 1) ? Wsrel : (m == 2) ? Wvroot : Wvrel;
    g_Wt[(m << 14) + (k << 7) + o] = src[(o << 7) + k];
}

// ---------------------------------------------------------------------------
// One thread per (edge, float4-chunk). 128 chunks per edge (4 channels x 128 f).
// Vector f32 atomics (sm_90+) -> 64M 16B REDs, coalesced per edge.
__global__ void aggregate_kernel(const float4* __restrict__ x4,
                                 const void* __restrict__ ei_raw) {
    long long tid = (long long)blockIdx.x * blockDim.x + threadIdx.x;
    int e = (int)(tid >> 7);
    int j = (int)(tid & 127);
    if (e >= NE) return;

    int r, c;
    if (g_is64) {
        const long long* ei = (const long long*)ei_raw;
        r = (int)ei[e];
        c = (int)ei[NE + e];
    } else {
        const int* ei = (const int*)ei_raw;
        r = ei[e];
        c = ei[NE + e];
    }

    float4 v = x4[c * 128 + j];
    float* dst = &g_agg[r * 512 + j * 4];
    asm volatile("red.global.add.v4.f32 [%0], {%1,%2,%3,%4};"
                 :: "l"(dst), "f"(v.x), "f"(v.y), "f"(v.z), "f"(v.w)
                 : "memory");
}

// ---------------------------------------------------------------------------
// Fused GEMM. Rows are (node, channel) pairs. Scalar rows (c=0) use
// W_s_root / W_s_rel (+bias); vector rows (c=1..3) use W_v_root / W_v_rel.
//   out_row = x_row @ Wroot^T + agg_row @ Wrel^T (+ b)
// Block: 64 rows x 128 outputs, 256 threads, thread = 8 rows x 4 outputs.
// FFMA2 (fma.rn.f32x2) packed fp32 math.
__device__ __forceinline__ int rowbase(int is_s, int r, int mlim) {
    r = (r < mlim) ? r : (mlim - 1);
    if (is_s) return r << 9;             // node n, channel 0
    int n = r / 3;
    int c = r - n * 3;
    return (n << 9) + ((c + 1) << 7);
}

#define TM 64
#define KT 32

__global__ __launch_bounds__(256, 2)
void gemm_kernel(const float* __restrict__ x,
                 const float* __restrict__ b_s,
                 float* __restrict__ out,
                 int nb_s) {
    __shared__ __align__(16) float As[TM][36];   // [row][k] pad 36 -> 4-phase stores
    __shared__ __align__(16) float Ws[KT][HH];   // [k][o]

    int t = threadIdx.x;
    int bid = (int)blockIdx.x;
    int is_s = (bid < nb_s) ? 1 : 0;
    int row0 = is_s ? bid * TM : (bid - nb_s) * TM;
    int mlim = is_s ? NN : 3 * NN;
    const float* Wroot = g_Wt + (is_s ? 0 : 2 * HH * HH);
    const float* Wrel  = g_Wt + (is_s ? HH * HH : 3 * HH * HH);

    int ox = t & 31;        // output group: outputs ox*4 .. ox*4+3
    int ry = t >> 5;        // row group: rows ry*8 .. ry*8+7 (warp <=> ry: A broadcast)
    int lr = t >> 3;        // loader row / W k-row (0..31)
    int lq = t & 7;         // loader float4 slot

    int cb[8];
    #pragma unroll
    for (int rr = 0; rr < 8; rr++) cb[rr] = rowbase(is_s, row0 + ry * 8 + rr, mlim);
    int lb0 = rowbase(is_s, row0 + lr, mlim);
    int lb1 = rowbase(is_s, row0 + 32 + lr, mlim);

    unsigned long long acc[8][2];
    #pragma unroll
    for (int rr = 0; rr < 8; rr++) { acc[rr][0] = 0ULL; acc[rr][1] = 0ULL; }

    #pragma unroll 1
    for (int half = 0; half < 2; half++) {
        const float* A = half ? g_agg : x;
        const float* W = half ? Wrel : Wroot;
        #pragma unroll 1
        for (int kc = 0; kc < HH; kc += KT) {
            __syncthreads();
            // A tile: 64 rows x 32 k
            float4 va0 = *(const float4*)(A + lb0 + kc + lq * 4);
            float4 va1 = *(const float4*)(A + lb1 + kc + lq * 4);
            *(float4*)(&As[lr][lq * 4]) = va0;
            *(float4*)(&As[32 + lr][lq * 4]) = va1;
            // W tile: 32 k-rows x 128 outputs (pre-transposed, coalesced)
            const float* wsrc = W + (kc + lr) * HH;
            #pragma unroll
            for (int s = 0; s < 4; s++) {
                float4 wv = *(const float4*)(wsrc + (lq + 8 * s) * 4);
                *(float4*)(&Ws[lr][(lq + 8 * s) * 4]) = wv;
            }
            __syncthreads();

            #pragma unroll
            for (int k4 = 0; k4 < KT; k4 += 4) {
                float4 a[8];
                #pragma unroll
                for (int rr = 0; rr < 8; rr++)
                    a[rr] = *(const float4*)(&As[ry * 8 + rr][k4]);   // warp broadcast
                ulonglong2 w[4];
                #pragma unroll
                for (int kk = 0; kk < 4; kk++)
                    w[kk] = *(const ulonglong2*)(&Ws[k4 + kk][ox * 4]);
                #pragma unroll
                for (int kk = 0; kk < 4; kk++) {
                    #pragma unroll
                    for (int rr = 0; rr < 8; rr++) {
                        float av = (kk == 0) ? a[rr].x : (kk == 1) ? a[rr].y
                                 : (kk == 2) ? a[rr].z : a[rr].w;
                        unsigned long long ap;
                        asm("mov.b64 %0, {%1, %1};" : "=l"(ap) : "f"(av));
                        asm("fma.rn.f32x2 %0, %1, %2, %0;"
                            : "+l"(acc[rr][0]) : "l"(ap), "l"(w[kk].x));
                        asm("fma.rn.f32x2 %0, %1, %2, %0;"
                            : "+l"(acc[rr][1]) : "l"(ap), "l"(w[kk].y));
                    }
                }
            }
        }
    }

    float4 bv = make_float4(0.f, 0.f, 0.f, 0.f);
    if (is_s) bv = *(const float4*)(b_s + ox * 4);
    #pragma unroll
    for (int rr = 0; rr < 8; rr++) {
        int r = row0 + ry * 8 + rr;
        if (r >= mlim) break;
        float o0, o1, o2, o3;
        asm("mov.b64 {%0,%1}, %2;" : "=f"(o0), "=f"(o1) : "l"(acc[rr][0]));
        asm("mov.b64 {%0,%1}, %2;" : "=f"(o2), "=f"(o3) : "l"(acc[rr][1]));
        float4 res = make_float4(o0 + bv.x, o1 + bv.y, o2 + bv.z, o3 + bv.w);
        *(float4*)(out + cb[rr] + ox * 4) = res;
    }
}

// ---------------------------------------------------------------------------
extern "C" void kernel_launch(void* const* d_in, const int* in_sizes, int n_in,
                              void* d_out, int out_size) {
    const float* x      = (const float*)d_in[0];
    const void*  ei     = d_in[1];
    const float* Wsrel  = (const float*)d_in[2];
    const float* Wsroot = (const float*)d_in[3];
    const float* bsroot = (const float*)d_in[4];
    const float* Wvrel  = (const float*)d_in[5];
    const float* Wvroot = (const float*)d_in[6];
    float* out = (float*)d_out;

    zero_agg_kernel<<<(NN * 128 + 255) / 256, 256>>>();
    probe_dtype_kernel<<<1, 32>>>((const int*)ei);
    transpose_w_kernel<<<(4 * HH * HH + 255) / 256, 256>>>(Wsroot, Wsrel, Wvroot, Wvrel);

    long long agg_threads = (long long)NE * 128;
    aggregate_kernel<<<(unsigned)(agg_threads / 256), 256>>>((const float4*)x, ei);

    int nb_s = (NN + TM - 1) / TM;            // 782
    int nb_v = (3 * NN + TM - 1) / TM;        // 2344
    gemm_kernel<<<nb_s + nb_v, 256>>>(x, bsroot, out, nb_s);
}

// round 2
// speedup vs baseline: 1.3980x; 1.3980x over previous
#include <cuda_runtime.h>

#define NN 50000
#define NE 500000
#define HH 128
// per-node row stride in floats: 4*H = 512

// Scratch (device globals — allocation-free rule)
__device__ float g_agg[NN * 512];            // aggregated raw neighbor features
__device__ float g_Wt[4 * HH * HH];          // transposed weights [m][k][o]
                                             // m: 0=W_s_root 1=W_s_rel 2=W_v_root 3=W_v_rel
__device__ int g_is64;                       // edge_index dtype flag

// ---------------------------------------------------------------------------
__global__ void zero_agg_kernel() {
    float4* p = reinterpret_cast<float4*>(g_agg);
    int n4 = NN * 128;
    int i = blockIdx.x * blockDim.x + threadIdx.x;
    if (i < n4) p[i] = make_float4(0.f, 0.f, 0.f, 0.f);
}

// ---------------------------------------------------------------------------
// Detect whether edge_index is int64 (JAX x64 on) or int32 (default).
__global__ void probe_dtype_kernel(const int* __restrict__ ei32) {
    if (threadIdx.x == 0 && blockIdx.x == 0) {
        int all_zero = 1;
        #pragma unroll
        for (int i = 0; i < 32; i++)
            if (ei32[2 * i + 1] != 0) all_zero = 0;
        g_is64 = all_zero;
    }
}

// ---------------------------------------------------------------------------
__global__ void transpose_w_kernel(const float* __restrict__ Wsroot,
                                   const float* __restrict__ Wsrel,
                                   const float* __restrict__ Wvroot,
                                   const float* __restrict__ Wvrel) {
    int t = blockIdx.x * blockDim.x + threadIdx.x;
    if (t >= 4 * HH * HH) return;
    int m = t >> 14;
    int rest = t & (HH * HH - 1);
    int o = rest >> 7;
    int k = rest & 127;
    const float* src = (m == 0) ? Wsroot : (m == 1) ? Wsrel : (m == 2) ? Wvroot : Wvrel;
    g_Wt[(m << 14) + (k << 7) + o] = src[(o << 7) + k];
}

// ---------------------------------------------------------------------------
// Channel-pass-blocked edge aggregation. One pass covers 32 float4 chunks
// (128 floats) of every edge's 512-float row, so the pass working set
// (~25 MB x-lines + ~25 MB agg-lines) stays L2-resident. Thread handles 4
// consecutive float4s (MLP=4): 8 threads per edge per pass.
__global__ void aggregate_kernel(const float4* __restrict__ x4,
                                 const void* __restrict__ ei_raw,
                                 int jbase4) {
    int tid = blockIdx.x * blockDim.x + threadIdx.x;
    int e = tid >> 3;
    int q = tid & 7;

    int r, c;
    if (g_is64) {
        const long long* ei = (const long long*)ei_raw;
        r = (int)ei[e];
        c = (int)ei[NE + e];
    } else {
        const int* ei = (const int*)ei_raw;
        r = ei[e];
        c = ei[NE + e];
    }

    const float4* src = x4 + (size_t)c * 128 + jbase4 + q * 4;
    float4 v0 = src[0];
    float4 v1 = src[1];
    float4 v2 = src[2];
    float4 v3 = src[3];

    float* dst = g_agg + (size_t)r * 512 + (size_t)(jbase4 + q * 4) * 4;
    asm volatile("red.global.add.v4.f32 [%0], {%1,%2,%3,%4};"
                 :: "l"(dst), "f"(v0.x), "f"(v0.y), "f"(v0.z), "f"(v0.w) : "memory");
    asm volatile("red.global.add.v4.f32 [%0], {%1,%2,%3,%4};"
                 :: "l"(dst + 4), "f"(v1.x), "f"(v1.y), "f"(v1.z), "f"(v1.w) : "memory");
    asm volatile("red.global.add.v4.f32 [%0], {%1,%2,%3,%4};"
                 :: "l"(dst + 8), "f"(v2.x), "f"(v2.y), "f"(v2.z), "f"(v2.w) : "memory");
    asm volatile("red.global.add.v4.f32 [%0], {%1,%2,%3,%4};"
                 :: "l"(dst + 12), "f"(v3.x), "f"(v3.y), "f"(v3.z), "f"(v3.w) : "memory");
}

// ---------------------------------------------------------------------------
// Fused GEMM: out_row = x_row @ Wroot^T + agg_row @ Wrel^T (+ b for scalar).
// Block: 64 rows x 128 outputs, 256 threads.
// Thread = 8 rows (4 row-PAIRS packed in f32x2 lanes) x 4 outputs.
// A tile stored k-major so a row pair is one broadcast LDS.64 — no A packing.
__device__ __forceinline__ int rowbase(int is_s, int r, int mlim) {
    r = (r < mlim) ? r : (mlim - 1);
    if (is_s) return r << 9;             // node n, channel 0
    int n = r / 3;
    int ch = r - n * 3;
    return (n << 9) + ((ch + 1) << 7);
}

#define TM 64
#define KT 32

__global__ __launch_bounds__(256, 2)
void gemm_kernel(const float* __restrict__ x,
                 const float* __restrict__ b_s,
                 float* __restrict__ out,
                 int nb_s) {
    __shared__ __align__(16) float As[KT][TM + 2];   // k-major, rows adjacent
    __shared__ __align__(16) float Ws[KT][HH];       // [k][o] pre-transposed

    int t = threadIdx.x;
    int bid = (int)blockIdx.x;
    int is_s = (bid < nb_s) ? 1 : 0;
    int row0 = is_s ? bid * TM : (bid - nb_s) * TM;
    int mlim = is_s ? NN : 3 * NN;
    const float* Wroot = g_Wt + (is_s ? 0 : 2 * HH * HH);
    const float* Wrel  = g_Wt + (is_s ? HH * HH : 3 * HH * HH);

    int ox = t & 31;        // output group: outputs ox*4 .. ox*4+3
    int ry = t >> 5;        // warp id: rows ry*8 .. ry*8+7 (A broadcast in warp)

    // A loader: thread loads 2 float4 of its row, scatters scalars k-major
    int alr = t >> 2;       // row 0..63
    int akq = t & 3;        // k-slot
    int ab = rowbase(is_s, row0 + alr, mlim);
    // W loader
    int wk = t >> 3;        // k row 0..31
    int wq = t & 7;

    unsigned long long acc[4][4];
    #pragma unroll
    for (int p = 0; p < 4; p++)
        #pragma unroll
        for (int j = 0; j < 4; j++) acc[p][j] = 0ULL;

    #pragma unroll 1
    for (int half = 0; half < 2; half++) {
        const float* A = half ? g_agg : x;
        const float* W = half ? Wrel : Wroot;
        #pragma unroll 1
        for (int kc = 0; kc < HH; kc += KT) {
            __syncthreads();
            // A tile 64 rows x 32 k, stored transposed (k-major)
            float4 a0 = *(const float4*)(A + ab + kc + akq * 4);
            float4 a1 = *(const float4*)(A + ab + kc + 16 + akq * 4);
            As[akq * 4 + 0][alr] = a0.x;
            As[akq * 4 + 1][alr] = a0.y;
            As[akq * 4 + 2][alr] = a0.z;
            As[akq * 4 + 3][alr] = a0.w;
            As[akq * 4 + 16][alr] = a1.x;
            As[akq * 4 + 17][alr] = a1.y;
            As[akq * 4 + 18][alr] = a1.z;
            As[akq * 4 + 19][alr] = a1.w;
            // W tile 32 k x 128 o, coalesced copy
            const float* wsrc = W + (kc + wk) * HH;
            #pragma unroll
            for (int s = 0; s < 4; s++) {
                float4 wv = *(const float4*)(wsrc + (wq + 8 * s) * 4);
                *(float4*)(&Ws[wk][(wq + 8 * s) * 4]) = wv;
            }
            __syncthreads();

            #pragma unroll
            for (int k = 0; k < KT; k++) {
                unsigned long long ap[4];
                #pragma unroll
                for (int p = 0; p < 4; p++)
                    ap[p] = *(const unsigned long long*)(&As[k][ry * 8 + 2 * p]);
                float4 w = *(const float4*)(&Ws[k][ox * 4]);
                #pragma unroll
                for (int j = 0; j < 4; j++) {
                    float wj = (j == 0) ? w.x : (j == 1) ? w.y : (j == 2) ? w.z : w.w;
                    unsigned long long wp;
                    asm("mov.b64 %0, {%1, %1};" : "=l"(wp) : "f"(wj));
                    #pragma unroll
                    for (int p = 0; p < 4; p++) {
                        asm("fma.rn.f32x2 %0, %1, %2, %0;"
                            : "+l"(acc[p][j]) : "l"(ap[p]), "l"(wp));
                    }
                }
            }
        }
    }

    float4 bv = make_float4(0.f, 0.f, 0.f, 0.f);
    if (is_s) bv = *(const float4*)(b_s + ox * 4);

    #pragma unroll
    for (int p = 0; p < 4; p++) {
        int ra = row0 + ry * 8 + 2 * p;
        int rb = ra + 1;
        float lo[4], hi[4];
        #pragma unroll
        for (int j = 0; j < 4; j++)
            asm("mov.b64 {%0,%1}, %2;" : "=f"(lo[j]), "=f"(hi[j]) : "l"(acc[p][j]));
        if (ra < mlim) {
            float4 res = make_float4(lo[0] + bv.x, lo[1] + bv.y, lo[2] + bv.z, lo[3] + bv.w);
            *(float4*)(out + rowbase(is_s, ra, mlim) + ox * 4) = res;
        }
        if (rb < mlim) {
            float4 res = make_float4(hi[0] + bv.x, hi[1] + bv.y, hi[2] + bv.z, hi[3] + bv.w);
            *(float4*)(out + rowbase(is_s, rb, mlim) + ox * 4) = res;
        }
    }
}

// ---------------------------------------------------------------------------
extern "C" void kernel_launch(void* const* d_in, const int* in_sizes, int n_in,
                              void* d_out, int out_size) {
    const float* x      = (const float*)d_in[0];
    const void*  ei     = d_in[1];
    const float* Wsrel  = (const float*)d_in[2];
    const float* Wsroot = (const float*)d_in[3];
    const float* bsroot = (const float*)d_in[4];
    const float* Wvrel  = (const float*)d_in[5];
    const float* Wvroot = (const float*)d_in[6];
    float* out = (float*)d_out;

    zero_agg_kernel<<<(NN * 128 + 255) / 256, 256>>>();
    probe_dtype_kernel<<<1, 32>>>((const int*)ei);
    transpose_w_kernel<<<(4 * HH * HH + 255) / 256, 256>>>(Wsroot, Wsrel, Wvroot, Wvrel);

    // 4 channel passes: per-pass working set ~50 MB -> L2-resident
    int agg_blocks = NE * 8 / 256;   // 15625
    aggregate_kernel<<<agg_blocks, 256>>>((const float4*)x, ei, 0);
    aggregate_kernel<<<agg_blocks, 256>>>((const float4*)x, ei, 32);
    aggregate_kernel<<<agg_blocks, 256>>>((const float4*)x, ei, 64);
    aggregate_kernel<<<agg_blocks, 256>>>((const float4*)x, ei, 96);

    int nb_s = (NN + TM - 1) / TM;            // 782
    int nb_v = (3 * NN + TM - 1) / TM;        // 2344
    gemm_kernel<<<nb_s + nb_v, 256>>>(x, bsroot, out, nb_s);
}

// round 5
// speedup vs baseline: 2.0559x; 1.4706x over previous
#include <cuda_runtime.h>

#define NN 50000
#define NE 500000
#define HH 128
// per-node row stride in floats: 4*H = 512

// Scratch (device globals — allocation-free rule)
__device__ float g_agg[NN * 512];            // aggregated raw neighbor features
__device__ float g_Wt[4 * HH * HH];          // transposed weights [m][k][o]
__device__ int g_is64;                       // edge_index dtype flag
__device__ int g_deg[NN];                    // degree histogram
__device__ int g_cur[NN];                    // scatter cursors
__device__ int g_off[NN + 1];                // CSR offsets
__device__ int g_ecol[NE];                   // CSR column lists (grouped by row)

__device__ __forceinline__ int clampn(int v) {
    return (v < 0) ? 0 : ((v >= NN) ? NN - 1 : v);
}

// ---------------------------------------------------------------------------
__global__ void zero_small_kernel() {
    int i = blockIdx.x * blockDim.x + threadIdx.x;
    if (i < NN) { g_deg[i] = 0; g_cur[i] = 0; }
}

// Detect whether edge_index is int64 (JAX x64 on) or int32 (default).
__global__ void probe_dtype_kernel(const int* __restrict__ ei32) {
    if (threadIdx.x == 0 && blockIdx.x == 0) {
        int all_zero = 1;
        #pragma unroll
        for (int i = 0; i < 32; i++)
            if (ei32[2 * i + 1] != 0) all_zero = 0;
        g_is64 = all_zero;
    }
}

__global__ void transpose_w_kernel(const float* __restrict__ Wsroot,
                                   const float* __restrict__ Wsrel,
                                   const float* __restrict__ Wvroot,
                                   const float* __restrict__ Wvrel) {
    int t = blockIdx.x * blockDim.x + threadIdx.x;
    if (t >= 4 * HH * HH) return;
    int m = t >> 14;
    int rest = t & (HH * HH - 1);
    int o = rest >> 7;
    int k = rest & 127;
    const float* src = (m == 0) ? Wsroot : (m == 1) ? Wsrel : (m == 2) ? Wvroot : Wvrel;
    g_Wt[(m << 14) + (k << 7) + o] = src[(o << 7) + k];
}

// ---------------------------------------------------------------------------
// CSR build: histogram -> exclusive scan -> scatter. All indices clamped so
// no input content can produce an out-of-bounds access.
__global__ void hist_kernel(const void* __restrict__ ei_raw) {
    int e = blockIdx.x * blockDim.x + threadIdx.x;
    if (e >= NE) return;
    int r = g_is64 ? (int)((const long long*)ei_raw)[e]
                   : ((const int*)ei_raw)[e];
    atomicAdd(&g_deg[clampn(r)], 1);
}

__global__ void scan_kernel() {
    __shared__ int sm[1024];
    int t = threadIdx.x;
    const int CH = (NN + 1023) / 1024;   // 49
    int b = t * CH;
    int e = min(b + CH, NN);
    int s = 0;
    for (int i = b; i < e; i++) s += g_deg[i];
    sm[t] = s;
    __syncthreads();
    for (int o = 1; o < 1024; o <<= 1) {
        int v = (t >= o) ? sm[t - o] : 0;
        __syncthreads();
        sm[t] += v;
        __syncthreads();
    }
    int run = (t == 0) ? 0 : sm[t - 1];
    for (int i = b; i < e; i++) { g_off[i] = run; run += g_deg[i]; }
    if (t == 1023) g_off[NN] = sm[1023];
}

__global__ void scatter_kernel(const void* __restrict__ ei_raw) {
    int e = blockIdx.x * blockDim.x + threadIdx.x;
    if (e >= NE) return;
    int r, c;
    if (g_is64) {
        const long long* ei = (const long long*)ei_raw;
        r = (int)ei[e];
        c = (int)ei[NE + e];
    } else {
        const int* ei = (const int*)ei_raw;
        r = ei[e];
        c = ei[NE + e];
    }
    r = clampn(r);
    c = clampn(c);
    int p = atomicAdd(&g_cur[r], 1);
    int slot = g_off[r] + p;
    // slot < g_off[r+1] <= NE by construction; clamp anyway (defensive).
    if (slot >= NE) slot = NE - 1;
    g_ecol[slot] = c;
}

// ---------------------------------------------------------------------------
// Atomic-free gather aggregation. Warp = (node, channel pass); lane owns one
// float4 of the node's 128-float pass chunk. Accumulate over the node's
// neighbor list in registers, single store at the end (also initializes agg).
// Pass is the slow-varying block index: blocks dispatch roughly in bid order,
// so each pass's 25.6 MB x-slice stays L2-resident.
#define GW 8
__global__ void gather_kernel(const float4* __restrict__ x4) {
    int w = threadIdx.x >> 5, lane = threadIdx.x & 31;
    const int ngb = NN / GW;            // 6250
    int bid = blockIdx.x;
    int pass = bid / ngb;
    int n = (bid - pass * ngb) * GW + w;
    int beg = g_off[n], end = g_off[n + 1];
    // Defensive clamps (no-op for valid CSR):
    if (beg < 0) beg = 0;
    if (end > NE) end = NE;
    int jo = (pass << 5) + lane;

    float4 a0 = make_float4(0.f, 0.f, 0.f, 0.f);
    float4 a1 = a0;
    int i = beg;
    for (; i + 2 <= end; i += 2) {
        int c0 = g_ecol[i];
        int c1 = g_ecol[i + 1];
        float4 v0 = x4[(size_t)c0 * 128 + jo];
        float4 v1 = x4[(size_t)c1 * 128 + jo];
        a0.x += v0.x; a0.y += v0.y; a0.z += v0.z; a0.w += v0.w;
        a1.x += v1.x; a1.y += v1.y; a1.z += v1.z; a1.w += v1.w;
    }
    if (i < end) {
        int c0 = g_ecol[i];
        float4 v0 = x4[(size_t)c0 * 128 + jo];
        a0.x += v0.x; a0.y += v0.y; a0.z += v0.z; a0.w += v0.w;
    }
    float4 r = make_float4(a0.x + a1.x, a0.y + a1.y, a0.z + a1.z, a0.w + a1.w);
    ((float4*)g_agg)[(size_t)n * 128 + jo] = r;
}

// ---------------------------------------------------------------------------
// Fused GEMM: out_row = x_row @ Wroot^T + agg_row @ Wrel^T (+ b for scalar).
// Block: 64 rows x 128 outputs, 256 threads.
// Thread = 8 rows (4 row-PAIRS packed in f32x2 lanes) x 4 outputs.
__device__ __forceinline__ int rowbase(int is_s, int r, int mlim) {
    r = (r < mlim) ? r : (mlim - 1);
    if (is_s) return r << 9;
    int n = r / 3;
    int ch = r - n * 3;
    return (n << 9) + ((ch + 1) << 7);
}

#define TM 64
#define KT 32

__global__ __launch_bounds__(256, 2)
void gemm_kernel(const float* __restrict__ x,
                 const float* __restrict__ b_s,
                 float* __restrict__ out,
                 int nb_s) {
    __shared__ __align__(16) float As[KT][TM + 2];   // k-major, rows adjacent
    __shared__ __align__(16) float Ws[KT][HH];       // [k][o] pre-transposed

    int t = threadIdx.x;
    int bid = (int)blockIdx.x;
    int is_s = (bid < nb_s) ? 1 : 0;
    int row0 = is_s ? bid * TM : (bid - nb_s) * TM;
    int mlim = is_s ? NN : 3 * NN;
    const float* Wroot = g_Wt + (is_s ? 0 : 2 * HH * HH);
    const float* Wrel  = g_Wt + (is_s ? HH * HH : 3 * HH * HH);

    int ox = t & 31;
    int ry = t >> 5;

    int alr = t >> 2;
    int akq = t & 3;
    int ab = rowbase(is_s, row0 + alr, mlim);
    int wk = t >> 3;
    int wq = t & 7;

    unsigned long long acc[4][4];
    #pragma unroll
    for (int p = 0; p < 4; p++)
        #pragma unroll
        for (int j = 0; j < 4; j++) acc[p][j] = 0ULL;

    #pragma unroll 1
    for (int half = 0; half < 2; half++) {
        const float* A = half ? g_agg : x;
        const float* W = half ? Wrel : Wroot;
        #pragma unroll 1
        for (int kc = 0; kc < HH; kc += KT) {
            __syncthreads();
            float4 a0 = *(const float4*)(A + ab + kc + akq * 4);
            float4 a1 = *(const float4*)(A + ab + kc + 16 + akq * 4);
            As[akq * 4 + 0][alr] = a0.x;
            As[akq * 4 + 1][alr] = a0.y;
            As[akq * 4 + 2][alr] = a0.z;
            As[akq * 4 + 3][alr] = a0.w;
            As[akq * 4 + 16][alr] = a1.x;
            As[akq * 4 + 17][alr] = a1.y;
            As[akq * 4 + 18][alr] = a1.z;
            As[akq * 4 + 19][alr] = a1.w;
            const float* wsrc = W + (kc + wk) * HH;
            #pragma unroll
            for (int s = 0; s < 4; s++) {
                float4 wv = *(const float4*)(wsrc + (wq + 8 * s) * 4);
                *(float4*)(&Ws[wk][(wq + 8 * s) * 4]) = wv;
            }
            __syncthreads();

            #pragma unroll
            for (int k = 0; k < KT; k++) {
                unsigned long long ap[4];
                #pragma unroll
                for (int p = 0; p < 4; p++)
                    ap[p] = *(const unsigned long long*)(&As[k][ry * 8 + 2 * p]);
                float4 w = *(const float4*)(&Ws[k][ox * 4]);
                #pragma unroll
                for (int j = 0; j < 4; j++) {
                    float wj = (j == 0) ? w.x : (j == 1) ? w.y : (j == 2) ? w.z : w.w;
                    unsigned long long wp;
                    asm("mov.b64 %0, {%1, %1};" : "=l"(wp) : "f"(wj));
                    #pragma unroll
                    for (int p = 0; p < 4; p++) {
                        asm("fma.rn.f32x2 %0, %1, %2, %0;"
                            : "+l"(acc[p][j]) : "l"(ap[p]), "l"(wp));
                    }
                }
            }
        }
    }

    float4 bv = make_float4(0.f, 0.f, 0.f, 0.f);
    if (is_s) bv = *(const float4*)(b_s + ox * 4);

    #pragma unroll
    for (int p = 0; p < 4; p++) {
        int ra = row0 + ry * 8 + 2 * p;
        int rb = ra + 1;
        float lo[4], hi[4];
        #pragma unroll
        for (int j = 0; j < 4; j++)
            asm("mov.b64 {%0,%1}, %2;" : "=f"(lo[j]), "=f"(hi[j]) : "l"(acc[p][j]));
        if (ra < mlim) {
            float4 res = make_float4(lo[0] + bv.x, lo[1] + bv.y, lo[2] + bv.z, lo[3] + bv.w);
            *(float4*)(out + rowbase(is_s, ra, mlim) + ox * 4) = res;
        }
        if (rb < mlim) {
            float4 res = make_float4(hi[0] + bv.x, hi[1] + bv.y, hi[2] + bv.z, hi[3] + bv.w);
            *(float4*)(out + rowbase(is_s, rb, mlim) + ox * 4) = res;
        }
    }
}

// ---------------------------------------------------------------------------
extern "C" void kernel_launch(void* const* d_in, const int* in_sizes, int n_in,
                              void* d_out, int out_size) {
    const float* x      = (const float*)d_in[0];
    const void*  ei     = d_in[1];
    const float* Wsrel  = (const float*)d_in[2];
    const float* Wsroot = (const float*)d_in[3];
    const float* bsroot = (const float*)d_in[4];
    const float* Wvrel  = (const float*)d_in[5];
    const float* Wvroot = (const float*)d_in[6];
    float* out = (float*)d_out;

    zero_small_kernel<<<(NN + 255) / 256, 256>>>();
    probe_dtype_kernel<<<1, 32>>>((const int*)ei);
    transpose_w_kernel<<<(4 * HH * HH + 255) / 256, 256>>>(Wsroot, Wsrel, Wvroot, Wvrel);

    // CSR build
    hist_kernel<<<(NE + 255) / 256, 256>>>(ei);
    scan_kernel<<<1, 1024>>>();
    scatter_kernel<<<(NE + 255) / 256, 256>>>(ei);

    // Atomic-free gather (4 channel passes folded into one launch, pass-major)
    gather_kernel<<<4 * (NN / GW), 256>>>((const float4*)x);

    int nb_s = (NN + TM - 1) / TM;            // 782
    int nb_v = (3 * NN + TM - 1) / TM;        // 2344
    gemm_kernel<<<nb_s + nb_v, 256>>>(x, bsroot, out, nb_s);
}